// round 9
// baseline (speedup 1.0000x reference)
#include <cuda_runtime.h>
#include <cuda_bf16.h>
#include <stdint.h>

// Embedding_44994077393181
// out[b,t,:] = W_emb_tok[ argnz(X[b,t,:]) , : ] + X_emb_pos[t,:]
// X: (2,2048,32000) fp32 one-hot; W: (32000,1024) fp32; pos: (2048,1024) fp32
//
// R8 engine + WORK-STEALING persistent CTAs.
// Per-row engine (unchanged from R8): 64-thread CTA, lock-step early-exit scan
// in 2048-float chunks, 8 independent uint4 loads/thread/pass, integer-OR
// nonzero detect (one-hot bits: 0x0 / 0x3F800000), fused gather + pos add.
// Scheduling (new): grid of 2960 CTAs; each processes its seed row then steals
// further rows from a global atomic counter. Removes the end-of-kernel
// parallelism decay caused by per-row runtime ~ idx (uniform).

#define VOCAB    32000
#define EMB_DIM  1024
#define CTX      2048
#define NROWS    4096         // BATCH * CTX
#define THREADS  64
#define CHUNKF4  512          // float4 per pass = 64 threads * 8  (2048 floats)
#define NPASS    16           // ceil(8000 / 512); last pass partial (320 f4)
#define NQ       8000         // float4 per row
#define GRID     2960         // ~20 CTAs per SM on 148-SM sm_100a

__device__ int g_next;

__global__ void reset_counter_kernel()
{
    g_next = GRID;            // rows [0, GRID) are seeded by blockIdx
}

__global__ __launch_bounds__(THREADS)
void embed_onehot_kernel(const float* __restrict__ X,
                         const float* __restrict__ W,
                         const float* __restrict__ pos,
                         float* __restrict__ out)
{
    const int tid = threadIdx.x;

    __shared__ int s_idx;
    __shared__ int s_row;

    int row = blockIdx.x;

    #pragma unroll 1
    while (row < NROWS) {
        const uint4* xv = reinterpret_cast<const uint4*>(X + (size_t)row * VOCAB);

        // ---- scan: find the one-hot index ----
        #pragma unroll 1
        for (int pass = 0; pass < NPASS; ++pass) {
            const int base = pass * CHUNKF4;

            // 8 independent 16B loads per thread (8 KB per CTA in flight).
            uint4 v[8];
            #pragma unroll
            for (int j = 0; j < 8; ++j) {
                const int p = base + j * THREADS + tid;
                if (p < NQ) {
                    v[j] = __ldcs(xv + p);
                } else {
                    v[j] = make_uint4(0u, 0u, 0u, 0u);
                }
            }

            // Cheap detect: OR-reduce raw bits (0x0 vs 0x3F800000).
            uint32_t acc = 0u;
            #pragma unroll
            for (int j = 0; j < 8; ++j)
                acc |= (v[j].x | v[j].y) | (v[j].z | v[j].w);

            // Rare path: pinpoint element from live registers.
            int found = -1;
            if (acc != 0u) {
                #pragma unroll
                for (int j = 0; j < 8; ++j) {
                    const int i = (base + j * THREADS + tid) << 2;
                    if (v[j].x) found = i;
                    if (v[j].y) found = i + 1;
                    if (v[j].z) found = i + 2;
                    if (v[j].w) found = i + 3;
                }
                s_idx = found;             // exactly one nonzero per row
            }

            if (__syncthreads_or(found >= 0)) break;
        }
        __syncthreads();                   // s_idx visible on the break path

        const int idx = s_idx;
        const int t   = row & (CTX - 1);

        // ---- fused gather + positional add: 64 threads * 4 float4 ----
        const float4* wrow = reinterpret_cast<const float4*>(W   + (size_t)idx * EMB_DIM);
        const float4* prow = reinterpret_cast<const float4*>(pos + (size_t)t   * EMB_DIM);
        float4*       orow = reinterpret_cast<float4*>(out + (size_t)row * EMB_DIM);

        #pragma unroll
        for (int j = 0; j < 4; ++j) {
            const int c = j * THREADS + tid;
            const float4 wv = __ldg(wrow + c);
            const float4 pv = __ldg(prow + c);
            float4 o;
            o.x = wv.x + pv.x;
            o.y = wv.y + pv.y;
            o.z = wv.z + pv.z;
            o.w = wv.w + pv.w;
            orow[c] = o;
        }

        // ---- steal next row ----
        if (tid == 0) s_row = atomicAdd(&g_next, 1);
        __syncthreads();
        row = s_row;
    }
}

extern "C" void kernel_launch(void* const* d_in, const int* in_sizes, int n_in,
                              void* d_out, int out_size)
{
    const float* X   = (const float*)d_in[0];   // (2,2048,32000)
    const float* W   = (const float*)d_in[1];   // (32000,1024)
    const float* pos = (const float*)d_in[2];   // (2048,1024)
    float* out = (float*)d_out;                 // (2,2048,1024)

    reset_counter_kernel<<<1, 1>>>();
    embed_onehot_kernel<<<GRID, THREADS>>>(X, W, pos, out);
}